// round 2
// baseline (speedup 1.0000x reference)
#include <cuda_runtime.h>
#include <math.h>

// ---------------------------------------------------------------------------
// EdgeMLPMPN: per-edge MLP
//   h = concat(x[src], x[tgt])            [256]
//   h1 = elu(h @ W1 + b1)                 [128]
//   h2 = elu(h1 @ W2 + b2)                [128]
//   out = h2 @ W3 + b3                    scalar
//
// Fused fp32 SIMT kernel using packed f32x2 FMA. 32 edges per CTA, 128
// threads. Channel-major smem tiles (pad 34 keeps 8B alignment for LDS.64
// and breaks bank conflicts). edge_index dtype (int32 vs int64) is sniffed
// at runtime: little-endian int64 with values < 2^31 has all-zero odd words.
// ---------------------------------------------------------------------------

#define EPT 32          // edges per tile (600000 % 32 == 0)
#define PAD 34          // smem row pad (even => LDS.64/STS.64 aligned)
#define SMEM_FLOATS (256 * PAD + 128 * PAD + 128)
#define SMEM_BYTES  (SMEM_FLOATS * 4)

__device__ __forceinline__ unsigned long long fma2(unsigned long long a,
                                                   unsigned long long b,
                                                   unsigned long long c) {
    unsigned long long d;
    asm("fma.rn.f32x2 %0, %1, %2, %3;" : "=l"(d) : "l"(a), "l"(b), "l"(c));
    return d;
}
__device__ __forceinline__ unsigned long long pack2(float lo, float hi) {
    unsigned long long d;
    asm("mov.b64 %0, {%1, %2};" : "=l"(d) : "f"(lo), "f"(hi));
    return d;
}
__device__ __forceinline__ float2 unpack2(unsigned long long v) {
    float2 r;
    asm("mov.b64 {%0, %1}, %2;" : "=f"(r.x), "=f"(r.y) : "l"(v));
    return r;
}
__device__ __forceinline__ float elu1(float v) {
    return v > 0.0f ? v : expm1f(v);
}

// GEMM over one tile: sOut[c][e] = elu( sum_k sA[k][e] * W[k][c] + bias[c] )
//   sA:   smem, [K][PAD] channel(k)-major, edges in the padded minor dim
//   W:    global, row-major [K][128]
//   sOut: smem, [128][PAD]
// Mapping: lane -> 4 output channels (4*lane..+3), warp -> 8 edges (8*wid..+7).
// Edge pairs packed into f32x2 lanes; W scalars duplicated into both halves.
template <int K>
__device__ __forceinline__ void gemm_elu(const float* sA,
                                         const float4* __restrict__ Wv,
                                         const float* __restrict__ bias,
                                         float* sOut, int wid, int lane) {
    unsigned long long acc[4][4];
#pragma unroll
    for (int i = 0; i < 4; i++)
#pragma unroll
        for (int p = 0; p < 4; p++) acc[i][p] = 0ull;

    const float* ar0 = sA + wid * 8;
#pragma unroll 2
    for (int k = 0; k < K; k++) {
        const float* ar = ar0 + k * PAD;
        unsigned long long a[4];
#pragma unroll
        for (int p = 0; p < 4; p++)
            a[p] = *reinterpret_cast<const unsigned long long*>(ar + 2 * p);  // broadcast LDS.64

        float4 w = __ldg(Wv + k * 32 + lane);  // coalesced 512B row per warp
        unsigned long long wp[4];
        wp[0] = pack2(w.x, w.x);
        wp[1] = pack2(w.y, w.y);
        wp[2] = pack2(w.z, w.z);
        wp[3] = pack2(w.w, w.w);

#pragma unroll
        for (int i = 0; i < 4; i++)
#pragma unroll
            for (int p = 0; p < 4; p++)
                acc[i][p] = fma2(a[p], wp[i], acc[i][p]);
    }

#pragma unroll
    for (int i = 0; i < 4; i++) {
        float b = __ldg(bias + 4 * lane + i);
#pragma unroll
        for (int p = 0; p < 4; p++) {
            float2 v = unpack2(acc[i][p]);
            v.x = elu1(v.x + b);
            v.y = elu1(v.y + b);
            *reinterpret_cast<float2*>(sOut + (4 * lane + i) * PAD + wid * 8 + 2 * p) = v;
        }
    }
}

__global__ void __launch_bounds__(128, 4)
edge_mlp_kernel(const float* __restrict__ x,
                const void* __restrict__ ei,
                const float* __restrict__ W1, const float* __restrict__ b1,
                const float* __restrict__ W2, const float* __restrict__ b2,
                const float* __restrict__ W3, const float* __restrict__ b3,
                float* __restrict__ out, int n_edges, int n_nodes) {
    extern __shared__ float smem[];
    float* xcat = smem;                          // [256][PAD] (k-major concat tile)
    float* h1   = smem + 256 * PAD;              // [128][PAD]
    float* red  = smem + 256 * PAD + 128 * PAD;  // [128]
    float* h2   = xcat;                          // reuse (xcat dead after GEMM1)

    const int wid  = threadIdx.x >> 5;
    const int lane = threadIdx.x & 31;
    const int tile = blockIdx.x * EPT;
    const int nv   = min(EPT, n_edges - tile);

    // --- sniff edge_index dtype: int64 (LE, values < 2^31) => odd words 0 ---
    const int* ei32 = (const int*)ei;
    const long long* ei64 = (const long long*)ei;
    int odd_or = 0;
#pragma unroll
    for (int i = 1; i < 64; i += 2) odd_or |= ei32[i];
    const bool is64 = (odd_or == 0);

    // --- gather: x[src] -> rows 0..127, x[tgt] -> rows 128..255 (k-major) ---
    for (int r = wid; r < 2 * nv; r += 4) {
        int e    = r >> 1;
        int half = r & 1;
        int pos  = half * n_edges + tile + e;
        long long node = is64 ? ei64[pos] : (long long)ei32[pos];
        // defensive clamp: never trap even if the sniff were wrong
        node = node < 0 ? 0 : (node >= n_nodes ? n_nodes - 1 : node);
        float4 v = __ldg(reinterpret_cast<const float4*>(x + node * 128) + lane);
        float* dst = xcat + (half * 128 + 4 * lane) * PAD + e;
        dst[0 * PAD] = v.x;
        dst[1 * PAD] = v.y;
        dst[2 * PAD] = v.z;
        dst[3 * PAD] = v.w;
    }
    __syncthreads();

    // --- layer 1: [32,256] @ [256,128] + elu ---
    gemm_elu<256>(xcat, reinterpret_cast<const float4*>(W1), b1, h1, wid, lane);
    __syncthreads();

    // --- layer 2: [32,128] @ [128,128] + elu (writes over xcat region) ---
    gemm_elu<128>(h1, reinterpret_cast<const float4*>(W2), b2, h2, wid, lane);
    __syncthreads();

    // --- layer 3: out[e] = h2[:,e] . W3 + b3 ---
    {
        float part = 0.0f;
        const int c0 = wid * 32;
#pragma unroll 8
        for (int c = 0; c < 32; c++)
            part += h2[(c0 + c) * PAD + lane] * __ldg(W3 + c0 + c);
        red[wid * 32 + lane] = part;
        __syncthreads();
        if (threadIdx.x < 32 && tile + lane < n_edges) {
            float s = red[lane] + red[32 + lane] + red[64 + lane] + red[96 + lane] + __ldg(b3);
            out[tile + lane] = s;
        }
    }
}

extern "C" void kernel_launch(void* const* d_in, const int* in_sizes, int n_in,
                              void* d_out, int out_size) {
    const float* x  = (const float*)d_in[0];
    const void*  ei = d_in[1];
    const float* W1 = (const float*)d_in[2];
    const float* b1 = (const float*)d_in[3];
    const float* W2 = (const float*)d_in[4];
    const float* b2 = (const float*)d_in[5];
    const float* W3 = (const float*)d_in[6];
    const float* b3 = (const float*)d_in[7];
    float* out = (float*)d_out;

    const int n_edges = out_size;             // one output per edge
    const int n_nodes = in_sizes[0] / 128;    // x is [n_nodes, 128]

    // Idempotent, deterministic attribute set (needed for >48KB dynamic smem).
    cudaFuncSetAttribute(edge_mlp_kernel,
                         cudaFuncAttributeMaxDynamicSharedMemorySize, SMEM_BYTES);

    const int grid = (n_edges + EPT - 1) / EPT;
    edge_mlp_kernel<<<grid, 128, SMEM_BYTES>>>(x, ei, W1, b1, W2, b2, W3, b3,
                                               out, n_edges, n_nodes);
}

// round 4
// speedup vs baseline: 1.5505x; 1.5505x over previous
#include <cuda_runtime.h>
#include <cuda_bf16.h>
#include <math.h>
#include <stdint.h>

// ---------------------------------------------------------------------------
// EdgeMLPMPN via mma.sync bf16x3-split (legacy HMMA path; tcgen05 is rejected
// by this harness's compute_103 virtual arch).
//   h  = concat(x[src], x[tgt])  [128, 256]
//   h1 = elu(h @ W1 + b1)        [128, 128]
//   h2 = elu(h1 @ W2 + b2)       [128, 128]
//   out= h2 @ W3 + b3            [128]
// fp32 operands split a = hi + lo (bf16); D accumulates hi*hi + hi*lo + lo*hi
// in fp32 registers (~1e-5 rel err). 8 warps: 4 m-slices x 2 n-slices.
// ---------------------------------------------------------------------------

#define EPT 128
#define THREADS 256
#define SA1 528   // A1 row stride (256 bf16 + 8 pad) -> ldmatrix conflict-free
#define SA2 272   // A2/h1 row stride (128 bf16 + 8 pad)
#define SW  272   // W tile row stride

#define SM_A_HI 0
#define SM_A_LO 67584                 // 128*528
#define SM_W_HI 135168                // SM_A_LO + 128*528
#define SM_W_LO (SM_W_HI + 34816)     // 128*272
#define SM_CTRL (SM_W_LO + 34816)     // = 204800
#define SM_SIDS (SM_CTRL)
#define SM_B1   (SM_CTRL + 1024)
#define SM_B2   (SM_B1 + 512)
#define SM_W3   (SM_B2 + 512)
#define SM_R0   (SM_W3 + 512)
#define SM_R1   (SM_R0 + 512)
#define SMEM_BYTES (SM_R1 + 512)

// transposed + bf16-split weights: WT[n][k], k contiguous
__device__ __align__(16) __nv_bfloat16 g_w1t_hi[128 * 256];
__device__ __align__(16) __nv_bfloat16 g_w1t_lo[128 * 256];
__device__ __align__(16) __nv_bfloat16 g_w2t_hi[128 * 128];
__device__ __align__(16) __nv_bfloat16 g_w2t_lo[128 * 128];

__device__ __forceinline__ uint32_t smem_u32(const void* p) {
    uint32_t a;
    asm("{ .reg .u64 t; cvta.to.shared.u64 t, %1; cvt.u32.u64 %0, t; }" : "=r"(a) : "l"(p));
    return a;
}
__device__ __forceinline__ void ldm_x4(uint32_t addr, uint32_t r[4]) {
    asm volatile("ldmatrix.sync.aligned.m8n8.x4.shared.b16 {%0,%1,%2,%3}, [%4];"
                 : "=r"(r[0]), "=r"(r[1]), "=r"(r[2]), "=r"(r[3]) : "r"(addr));
}
__device__ __forceinline__ void hmma(float c[4], const uint32_t a[4],
                                     uint32_t b0, uint32_t b1) {
    asm volatile(
        "mma.sync.aligned.m16n8k16.row.col.f32.bf16.bf16.f32 "
        "{%0,%1,%2,%3}, {%4,%5,%6,%7}, {%8,%9}, {%0,%1,%2,%3};"
        : "+f"(c[0]), "+f"(c[1]), "+f"(c[2]), "+f"(c[3])
        : "r"(a[0]), "r"(a[1]), "r"(a[2]), "r"(a[3]), "r"(b0), "r"(b1));
}
__device__ __forceinline__ float elu1(float v) { return v > 0.0f ? v : expm1f(v); }
__device__ __forceinline__ void split_bf16(float v, __nv_bfloat16& hi, __nv_bfloat16& lo) {
    hi = __float2bfloat16_rn(v);
    lo = __float2bfloat16_rn(v - __bfloat162float(hi));
}
union BF4 { __nv_bfloat16 b[4]; unsigned long long u; };
union BF2 { __nv_bfloat16 b[2]; uint32_t u; };

// ---------------- prologue: transpose + bf16-split W1, W2 ----------------
__global__ void wconv_kernel(const float* __restrict__ W1, const float* __restrict__ W2) {
    int i = blockIdx.x * blockDim.x + threadIdx.x;
    if (i < 32768) {                     // W1T[n][k] <- W1[k][n], [128][256]
        int n = i >> 8, k = i & 255;
        float v = __ldg(W1 + k * 128 + n);
        __nv_bfloat16 h, l; split_bf16(v, h, l);
        g_w1t_hi[i] = h; g_w1t_lo[i] = l;
    } else if (i < 49152) {              // W2T[n][k] <- W2[k][n], [128][128]
        int j = i - 32768;
        int n = j >> 7, k = j & 127;
        float v = __ldg(W2 + k * 128 + n);
        __nv_bfloat16 h, l; split_bf16(v, h, l);
        g_w2t_hi[j] = h; g_w2t_lo[j] = l;
    }
}

// stage one [128 n][128 k] hi/lo W chunk (row-major, row_elems k per row)
__device__ __forceinline__ void stage_w(char* smem,
                                        const __nv_bfloat16* __restrict__ gh,
                                        const __nv_bfloat16* __restrict__ gl,
                                        int row_elems, int col0, int tid) {
#pragma unroll
    for (int it = 0; it < 8; it++) {
        int idx = tid + it * THREADS;     // 0..2047
        int n = idx >> 4, j = idx & 15;   // j: 16B chunk within 256B row
        uint4 vh = __ldg(reinterpret_cast<const uint4*>(gh + n * row_elems + col0) + j);
        uint4 vl = __ldg(reinterpret_cast<const uint4*>(gl + n * row_elems + col0) + j);
        *reinterpret_cast<uint4*>(smem + SM_W_HI + n * SW + j * 16) = vh;
        *reinterpret_cast<uint4*>(smem + SM_W_LO + n * SW + j * 16) = vl;
    }
}

// run one 3-pass split GEMM block: KT k-tiles, A stride sa, accumulate into acc
// a_hi/a_lo/b_hi/b_lo are smem byte bases; k0byte added to A column offset.
__device__ __forceinline__ void gemm_3pass(uint32_t sb, uint32_t a_hi, uint32_t a_lo,
                                           int sa, int k0byte, int KT,
                                           int e0, int n0, int lane,
                                           float acc[2][8][4]) {
    const int rowA = lane & 15;
    const int chA = (lane >> 4) * 16;
    const int rowB = (lane & 7) + ((lane >> 4) << 3);
    const int chB = ((lane >> 3) & 1) * 16;

#pragma unroll
    for (int p = 0; p < 3; p++) {
        uint32_t ab = (p == 2) ? a_lo : a_hi;
        uint32_t bb = sb + ((p == 1) ? SM_W_LO : SM_W_HI);
        uint32_t abase0 = ab + (e0 + rowA) * sa + chA + k0byte;
        uint32_t abase1 = ab + (e0 + 16 + rowA) * sa + chA + k0byte;
        uint32_t bbase = bb + (n0 + rowB) * SW + chB;
#pragma unroll
        for (int kt = 0; kt < 8; kt++) {
            if (kt >= KT) break;
            uint32_t a0[4], a1[4];
            ldm_x4(abase0 + kt * 32, a0);
            ldm_x4(abase1 + kt * 32, a1);
#pragma unroll
            for (int ntp = 0; ntp < 4; ntp++) {
                uint32_t b[4];
                ldm_x4(bbase + ntp * 16 * SW + kt * 32, b);
                hmma(acc[0][2 * ntp + 0], a0, b[0], b[1]);
                hmma(acc[0][2 * ntp + 1], a0, b[2], b[3]);
                hmma(acc[1][2 * ntp + 0], a1, b[0], b[1]);
                hmma(acc[1][2 * ntp + 1], a1, b[2], b[3]);
            }
        }
    }
}

__global__ void __launch_bounds__(THREADS, 1)
edge_mlp_hmma_kernel(const float* __restrict__ x, const void* __restrict__ ei,
                     const float* __restrict__ b1, const float* __restrict__ b2,
                     const float* __restrict__ W3, const float* __restrict__ b3,
                     float* __restrict__ out, int n_edges, int n_nodes) {
    extern __shared__ char smem[];
    const uint32_t sb = smem_u32(smem);
    const int tid = threadIdx.x, wid = tid >> 5, lane = tid & 31;
    const int gid = lane >> 2, tig = lane & 3;
    const int mw = wid >> 1, nw = wid & 1;
    const int e0 = mw * 32, n0 = nw * 64;
    const int tile = blockIdx.x * EPT;
    const int nv = min(EPT, n_edges - tile);

    // sniff edge_index dtype (int64 LE values < 2^31 => odd 32-bit words all 0)
    const int* ei32 = (const int*)ei;
    const long long* ei64 = (const long long*)ei;
    int odd_or = 0;
#pragma unroll
    for (int i = 1; i < 64; i += 2) odd_or |= ei32[i];
    const bool is64 = (odd_or == 0);

    int* sids = (int*)(smem + SM_SIDS);
    {
        int half = tid >> 7, e = tid & 127;
        int ec = e < nv ? e : (nv - 1);
        int pos = half * n_edges + tile + ec;
        long long node = is64 ? ei64[pos] : (long long)ei32[pos];
        node = node < 0 ? 0 : (node >= n_nodes ? (long long)n_nodes - 1 : node);
        sids[tid] = (int)node;
    }
    float* b1s = (float*)(smem + SM_B1);
    float* b2s = (float*)(smem + SM_B2);
    float* w3s = (float*)(smem + SM_W3);
    if (tid < 128) {
        b1s[tid] = __ldg(b1 + tid);
        b2s[tid] = __ldg(b2 + tid);
        w3s[tid] = __ldg(W3 + tid);
    }
    __syncthreads();

    // ---- gather + split: A1 [128 e][256 k] bf16 hi/lo, row stride 528B ----
    const float4* x4 = reinterpret_cast<const float4*>(x);
#pragma unroll 4
    for (int it = 0; it < 32; it++) {
        int idx = tid + it * THREADS;      // 0..8191 = 128 e x 64 quads
        int e = idx >> 6, q = idx & 63;
        int half = q >> 5, kq = q & 31;
        int node = sids[half * 128 + e];
        float4 v = __ldg(x4 + node * 32 + kq);
        int k = q * 4;                      // 0..252
        BF4 h, l;
        split_bf16(v.x, h.b[0], l.b[0]);
        split_bf16(v.y, h.b[1], l.b[1]);
        split_bf16(v.z, h.b[2], l.b[2]);
        split_bf16(v.w, h.b[3], l.b[3]);
        *reinterpret_cast<unsigned long long*>(smem + SM_A_HI + e * SA1 + k * 2) = h.u;
        *reinterpret_cast<unsigned long long*>(smem + SM_A_LO + e * SA1 + k * 2) = l.u;
    }

    float acc[2][8][4];
#pragma unroll
    for (int i = 0; i < 2; i++)
#pragma unroll
        for (int j = 0; j < 8; j++)
#pragma unroll
            for (int q = 0; q < 4; q++) acc[i][j][q] = 0.0f;

    // ---- layer 1: two 128-k W chunks ----
    stage_w(smem, g_w1t_hi, g_w1t_lo, 256, 0, tid);
    __syncthreads();
    gemm_3pass(sb, sb + SM_A_HI, sb + SM_A_LO, SA1, 0, 8, e0, n0, lane, acc);
    __syncthreads();
    stage_w(smem, g_w1t_hi, g_w1t_lo, 256, 128, tid);
    __syncthreads();
    gemm_3pass(sb, sb + SM_A_HI, sb + SM_A_LO, SA1, 256, 8, e0, n0, lane, acc);

    // ---- epilogue 1: bias + elu, re-split into A2 (h1) over A region ----
    // thread owns rows {gid, gid+8} of each m-tile, cols {2tig, 2tig+1} of each n-tile
#pragma unroll
    for (int mt = 0; mt < 2; mt++) {
#pragma unroll
        for (int nt = 0; nt < 8; nt++) {
            int nc = n0 + 8 * nt + 2 * tig;
            int ea = e0 + 16 * mt + gid, eb = ea + 8;
            float v00 = elu1(acc[mt][nt][0] + b1s[nc]);
            float v01 = elu1(acc[mt][nt][1] + b1s[nc + 1]);
            float v10 = elu1(acc[mt][nt][2] + b1s[nc]);
            float v11 = elu1(acc[mt][nt][3] + b1s[nc + 1]);
            BF2 h, l;
            split_bf16(v00, h.b[0], l.b[0]);
            split_bf16(v01, h.b[1], l.b[1]);
            *reinterpret_cast<uint32_t*>(smem + SM_A_HI + ea * SA2 + nc * 2) = h.u;
            *reinterpret_cast<uint32_t*>(smem + SM_A_LO + ea * SA2 + nc * 2) = l.u;
            split_bf16(v10, h.b[0], l.b[0]);
            split_bf16(v11, h.b[1], l.b[1]);
            *reinterpret_cast<uint32_t*>(smem + SM_A_HI + eb * SA2 + nc * 2) = h.u;
            *reinterpret_cast<uint32_t*>(smem + SM_A_LO + eb * SA2 + nc * 2) = l.u;
        }
    }
    __syncthreads();

    // ---- layer 2 ----
    stage_w(smem, g_w2t_hi, g_w2t_lo, 128, 0, tid);
    __syncthreads();
#pragma unroll
    for (int i = 0; i < 2; i++)
#pragma unroll
        for (int j = 0; j < 8; j++)
#pragma unroll
            for (int q = 0; q < 4; q++) acc[i][j][q] = 0.0f;
    gemm_3pass(sb, sb + SM_A_HI, sb + SM_A_LO, SA2, 0, 8, e0, n0, lane, acc);

    // ---- epilogue 2: bias + elu + dot(W3), butterfly-reduce over tig ----
    float pa[2] = {0.0f, 0.0f}, pb[2] = {0.0f, 0.0f};
#pragma unroll
    for (int mt = 0; mt < 2; mt++) {
#pragma unroll
        for (int nt = 0; nt < 8; nt++) {
            int nc = n0 + 8 * nt + 2 * tig;
            float w0 = w3s[nc], w1 = w3s[nc + 1];
            pa[mt] += elu1(acc[mt][nt][0] + b2s[nc]) * w0
                    + elu1(acc[mt][nt][1] + b2s[nc + 1]) * w1;
            pb[mt] += elu1(acc[mt][nt][2] + b2s[nc]) * w0
                    + elu1(acc[mt][nt][3] + b2s[nc + 1]) * w1;
        }
    }
#pragma unroll
    for (int mt = 0; mt < 2; mt++) {
        pa[mt] += __shfl_xor_sync(0xffffffff, pa[mt], 1);
        pa[mt] += __shfl_xor_sync(0xffffffff, pa[mt], 2);
        pb[mt] += __shfl_xor_sync(0xffffffff, pb[mt], 1);
        pb[mt] += __shfl_xor_sync(0xffffffff, pb[mt], 2);
    }
    float* red = (float*)(smem + (nw ? SM_R1 : SM_R0));
    if (tig == 0) {
#pragma unroll
        for (int mt = 0; mt < 2; mt++) {
            red[e0 + 16 * mt + gid] = pa[mt];
            red[e0 + 16 * mt + gid + 8] = pb[mt];
        }
    }
    __syncthreads();
    if (tid < 128 && tid < nv) {
        float* r0 = (float*)(smem + SM_R0);
        float* r1 = (float*)(smem + SM_R1);
        out[tile + tid] = r0[tid] + r1[tid] + __ldg(b3);
    }
}

extern "C" void kernel_launch(void* const* d_in, const int* in_sizes, int n_in,
                              void* d_out, int out_size) {
    const float* x  = (const float*)d_in[0];
    const void*  ei = d_in[1];
    const float* W1 = (const float*)d_in[2];
    const float* b1 = (const float*)d_in[3];
    const float* W2 = (const float*)d_in[4];
    const float* b2 = (const float*)d_in[5];
    const float* W3 = (const float*)d_in[6];
    const float* b3 = (const float*)d_in[7];
    float* out = (float*)d_out;

    const int n_edges = out_size;
    const int n_nodes = in_sizes[0] / 128;

    cudaFuncSetAttribute(edge_mlp_hmma_kernel,
                         cudaFuncAttributeMaxDynamicSharedMemorySize, SMEM_BYTES);

    wconv_kernel<<<192, 256>>>(W1, W2);
    const int grid = (n_edges + EPT - 1) / EPT;
    edge_mlp_hmma_kernel<<<grid, THREADS, SMEM_BYTES>>>(x, ei, b1, b2, W3, b3,
                                                        out, n_edges, n_nodes);
}

// round 5
// speedup vs baseline: 2.1970x; 1.4170x over previous
#include <cuda_runtime.h>
#include <cuda_bf16.h>
#include <math.h>
#include <stdint.h>

// ---------------------------------------------------------------------------
// EdgeMLPMPN via mma.sync bf16x3-split (hi*hi + hi*lo + lo*hi, fp32 acc).
// R5: EPT=64, 2 CTAs/SM (smem ~104KB), W staged in 64k-chunks via cp.async,
// fragment sharing across the 3 split passes (LDSM 18->10 per k-tile).
// 8 warps/CTA: 4 m-slices (16 edges) x 2 n-slices (64 ch).
// ---------------------------------------------------------------------------

#define EPT 64
#define THREADS 256
#define SA1 528   // A1 row stride bytes (256 bf16 + pad); 33x16B -> ldm conflict-free
#define SA2 272   // h1 row stride (128 bf16 + pad); 17x16B
#define SWS 144   // W chunk row stride (64 bf16 + pad); 9x16B

#define SM_A_HI 0
#define SM_A_LO 33792                  // 64*528
#define SM_W_HI 67584
#define SM_W_LO (SM_W_HI + 18432)      // 128*144
#define SM_CTRL (SM_W_LO + 18432)      // 104448
#define SM_SIDS (SM_CTRL)              // 128 ints
#define SM_B1   (SM_CTRL + 512)
#define SM_B2   (SM_B1 + 512)
#define SM_W3   (SM_B2 + 512)
#define SM_R0   (SM_W3 + 512)
#define SM_R1   (SM_R0 + 256)
#define SMEM_BYTES (SM_R1 + 256)       // 104.5KB -> 2 CTAs/SM

// transposed + bf16-split weights: WT[n][k], k contiguous
__device__ __align__(16) __nv_bfloat16 g_w1t_hi[128 * 256];
__device__ __align__(16) __nv_bfloat16 g_w1t_lo[128 * 256];
__device__ __align__(16) __nv_bfloat16 g_w2t_hi[128 * 128];
__device__ __align__(16) __nv_bfloat16 g_w2t_lo[128 * 128];

__device__ __forceinline__ uint32_t smem_u32(const void* p) {
    uint32_t a;
    asm("{ .reg .u64 t; cvta.to.shared.u64 t, %1; cvt.u32.u64 %0, t; }" : "=r"(a) : "l"(p));
    return a;
}
__device__ __forceinline__ void ldm_x4(uint32_t addr, uint32_t r[4]) {
    asm volatile("ldmatrix.sync.aligned.m8n8.x4.shared.b16 {%0,%1,%2,%3}, [%4];"
                 : "=r"(r[0]), "=r"(r[1]), "=r"(r[2]), "=r"(r[3]) : "r"(addr));
}
__device__ __forceinline__ void hmma(float c[4], const uint32_t a[4],
                                     uint32_t b0, uint32_t b1) {
    asm volatile(
        "mma.sync.aligned.m16n8k16.row.col.f32.bf16.bf16.f32 "
        "{%0,%1,%2,%3}, {%4,%5,%6,%7}, {%8,%9}, {%0,%1,%2,%3};"
        : "+f"(c[0]), "+f"(c[1]), "+f"(c[2]), "+f"(c[3])
        : "r"(a[0]), "r"(a[1]), "r"(a[2]), "r"(a[3]), "r"(b0), "r"(b1));
}
__device__ __forceinline__ void cp16(uint32_t dst, const void* src) {
    asm volatile("cp.async.cg.shared.global [%0], [%1], 16;" :: "r"(dst), "l"(src));
}
__device__ __forceinline__ void cp_commit() {
    asm volatile("cp.async.commit_group;" ::: "memory");
}
__device__ __forceinline__ void cp_wait0() {
    asm volatile("cp.async.wait_group 0;" ::: "memory");
}
__device__ __forceinline__ float elu1(float v) { return v > 0.0f ? v : expm1f(v); }
__device__ __forceinline__ void split_bf16(float v, __nv_bfloat16& hi, __nv_bfloat16& lo) {
    hi = __float2bfloat16_rn(v);
    lo = __float2bfloat16_rn(v - __bfloat162float(hi));
}
union BF4 { __nv_bfloat16 b[4]; unsigned long long u; };
union BF2 { __nv_bfloat16 b[2]; uint32_t u; };

// ---------------- prologue: transpose + bf16-split W1, W2 ----------------
__global__ void wconv_kernel(const float* __restrict__ W1, const float* __restrict__ W2) {
    int i = blockIdx.x * blockDim.x + threadIdx.x;
    if (i < 32768) {                     // W1T[n][k] <- W1[k][n], [128][256]
        int n = i >> 8, k = i & 255;
        float v = __ldg(W1 + k * 128 + n);
        __nv_bfloat16 h, l; split_bf16(v, h, l);
        g_w1t_hi[i] = h; g_w1t_lo[i] = l;
    } else if (i < 49152) {              // W2T[n][k] <- W2[k][n], [128][128]
        int j = i - 32768;
        int n = j >> 7, k = j & 127;
        float v = __ldg(W2 + k * 128 + n);
        __nv_bfloat16 h, l; split_bf16(v, h, l);
        g_w2t_hi[j] = h; g_w2t_lo[j] = l;
    }
}

// async-stage one [128 n][64 k] hi/lo W chunk (global row stride row_elems)
__device__ __forceinline__ void stage_w_async(uint32_t sb,
                                              const __nv_bfloat16* __restrict__ gh,
                                              const __nv_bfloat16* __restrict__ gl,
                                              int row_elems, int col0, int tid) {
#pragma unroll
    for (int it = 0; it < 4; it++) {
        int idx = tid + it * THREADS;     // 0..1023
        int n = idx >> 3, j = idx & 7;    // j: 16B chunk within 128B row
        cp16(sb + SM_W_HI + n * SWS + j * 16, gh + n * row_elems + col0 + j * 8);
        cp16(sb + SM_W_LO + n * SWS + j * 16, gl + n * row_elems + col0 + j * 8);
    }
    cp_commit();
}

// one 64-k stage (4 k-tiles) of the 3-pass split GEMM; fragments shared.
__device__ __forceinline__ void gemm_stage(uint32_t sb, int sa, int a_k0byte,
                                           int e0, int n0, int lane,
                                           float acc[8][4]) {
    const int rowA = lane & 15;
    const int chA = (lane >> 4) * 16;
    const int rowB = (lane & 7) + ((lane >> 4) << 3);
    const int chB = ((lane >> 3) & 1) * 16;

    uint32_t aH = sb + SM_A_HI + (e0 + rowA) * sa + chA + a_k0byte;
    uint32_t aL = sb + SM_A_LO + (e0 + rowA) * sa + chA + a_k0byte;
    uint32_t bH = sb + SM_W_HI + (n0 + rowB) * SWS + chB;
    uint32_t bL = sb + SM_W_LO + (n0 + rowB) * SWS + chB;

#pragma unroll
    for (int kt = 0; kt < 4; kt++) {
        uint32_t ah[4], al[4];
        ldm_x4(aH + kt * 32, ah);
        ldm_x4(aL + kt * 32, al);
#pragma unroll
        for (int ntp = 0; ntp < 4; ntp++) {
            uint32_t bh[4], bl[4];
            ldm_x4(bH + ntp * 16 * SWS + kt * 32, bh);
            ldm_x4(bL + ntp * 16 * SWS + kt * 32, bl);
            hmma(acc[2 * ntp + 0], ah, bh[0], bh[1]);
            hmma(acc[2 * ntp + 1], ah, bh[2], bh[3]);
            hmma(acc[2 * ntp + 0], ah, bl[0], bl[1]);
            hmma(acc[2 * ntp + 1], ah, bl[2], bl[3]);
            hmma(acc[2 * ntp + 0], al, bh[0], bh[1]);
            hmma(acc[2 * ntp + 1], al, bh[2], bh[3]);
        }
    }
}

__global__ void __launch_bounds__(THREADS, 2)
edge_mlp_hmma_kernel(const float* __restrict__ x, const void* __restrict__ ei,
                     const float* __restrict__ b1, const float* __restrict__ b2,
                     const float* __restrict__ W3, const float* __restrict__ b3,
                     float* __restrict__ out, int n_edges, int n_nodes) {
    extern __shared__ char smem[];
    const uint32_t sb = smem_u32(smem);
    const int tid = threadIdx.x, wid = tid >> 5, lane = tid & 31;
    const int gid = lane >> 2, tig = lane & 3;
    const int mw = wid >> 1, nw = wid & 1;
    const int e0 = mw * 16, n0 = nw * 64;
    const int tile = blockIdx.x * EPT;
    const int nv = min(EPT, n_edges - tile);

    // sniff edge_index dtype (int64 LE values < 2^31 => odd 32-bit words all 0)
    const int* ei32 = (const int*)ei;
    const long long* ei64 = (const long long*)ei;
    int odd_or = 0;
#pragma unroll
    for (int i = 1; i < 64; i += 2) odd_or |= ei32[i];
    const bool is64 = (odd_or == 0);

    int* sids = (int*)(smem + SM_SIDS);
    float* b1s = (float*)(smem + SM_B1);
    float* b2s = (float*)(smem + SM_B2);
    float* w3s = (float*)(smem + SM_W3);
    if (tid < 128) {
        int half = tid >> 6, e = tid & 63;
        int ec = e < nv ? e : (nv - 1);
        int pos = half * n_edges + tile + ec;
        long long node = is64 ? ei64[pos] : (long long)ei32[pos];
        node = node < 0 ? 0 : (node >= n_nodes ? (long long)n_nodes - 1 : node);
        sids[tid] = (int)node;
        b1s[tid] = __ldg(b1 + tid);
        b2s[tid] = __ldg(b2 + tid);
        w3s[tid] = __ldg(W3 + tid);
    }
    __syncthreads();

    // prefetch W1 chunk 0 while gathering A
    stage_w_async(sb, g_w1t_hi, g_w1t_lo, 256, 0, tid);

    // ---- gather + split: A1 [64 e][256 k] bf16 hi/lo ----
    const float4* x4 = reinterpret_cast<const float4*>(x);
#pragma unroll 4
    for (int it = 0; it < 16; it++) {
        int idx = tid + it * THREADS;      // 0..4095 = 64 e x 64 quads
        int e = idx >> 6, q = idx & 63;
        int half = q >> 5, kq = q & 31;
        int node = sids[half * 64 + e];
        float4 v = __ldg(x4 + node * 32 + kq);
        int k = q * 4;
        BF4 h, l;
        split_bf16(v.x, h.b[0], l.b[0]);
        split_bf16(v.y, h.b[1], l.b[1]);
        split_bf16(v.z, h.b[2], l.b[2]);
        split_bf16(v.w, h.b[3], l.b[3]);
        *reinterpret_cast<unsigned long long*>(smem + SM_A_HI + e * SA1 + k * 2) = h.u;
        *reinterpret_cast<unsigned long long*>(smem + SM_A_LO + e * SA1 + k * 2) = l.u;
    }
    cp_wait0();
    __syncthreads();

    float acc[8][4];
#pragma unroll
    for (int j = 0; j < 8; j++)
#pragma unroll
        for (int q = 0; q < 4; q++) acc[j][q] = 0.0f;

    // ---- layer 1: four 64-k stages ----
#pragma unroll 1
    for (int c = 0; c < 4; c++) {
        gemm_stage(sb, SA1, c * 128, e0, n0, lane, acc);
        __syncthreads();
        if (c < 3) {
            stage_w_async(sb, g_w1t_hi, g_w1t_lo, 256, (c + 1) * 64, tid);
            cp_wait0();
            __syncthreads();
        }
    }

    // prefetch W2 chunk 0; overlap with epilogue-1 resplit
    stage_w_async(sb, g_w2t_hi, g_w2t_lo, 128, 0, tid);

    // ---- epilogue 1: bias + elu, re-split h1 into A region (stride SA2) ----
#pragma unroll
    for (int nt = 0; nt < 8; nt++) {
        int nc = n0 + 8 * nt + 2 * tig;
        int ea = e0 + gid, eb = ea + 8;
        float v00 = elu1(acc[nt][0] + b1s[nc]);
        float v01 = elu1(acc[nt][1] + b1s[nc + 1]);
        float v10 = elu1(acc[nt][2] + b1s[nc]);
        float v11 = elu1(acc[nt][3] + b1s[nc + 1]);
        BF2 h, l;
        split_bf16(v00, h.b[0], l.b[0]);
        split_bf16(v01, h.b[1], l.b[1]);
        *reinterpret_cast<uint32_t*>(smem + SM_A_HI + ea * SA2 + nc * 2) = h.u;
        *reinterpret_cast<uint32_t*>(smem + SM_A_LO + ea * SA2 + nc * 2) = l.u;
        split_bf16(v10, h.b[0], l.b[0]);
        split_bf16(v11, h.b[1], l.b[1]);
        *reinterpret_cast<uint32_t*>(smem + SM_A_HI + eb * SA2 + nc * 2) = h.u;
        *reinterpret_cast<uint32_t*>(smem + SM_A_LO + eb * SA2 + nc * 2) = l.u;
    }
#pragma unroll
    for (int j = 0; j < 8; j++)
#pragma unroll
        for (int q = 0; q < 4; q++) acc[j][q] = 0.0f;
    cp_wait0();
    __syncthreads();

    // ---- layer 2: two 64-k stages ----
#pragma unroll 1
    for (int c = 0; c < 2; c++) {
        gemm_stage(sb, SA2, c * 128, e0, n0, lane, acc);
        __syncthreads();
        if (c == 0) {
            stage_w_async(sb, g_w2t_hi, g_w2t_lo, 128, 64, tid);
            cp_wait0();
            __syncthreads();
        }
    }

    // ---- epilogue 2: bias + elu + dot(W3), butterfly over tig ----
    float pa = 0.0f, pb = 0.0f;
#pragma unroll
    for (int nt = 0; nt < 8; nt++) {
        int nc = n0 + 8 * nt + 2 * tig;
        float w0 = w3s[nc], w1 = w3s[nc + 1];
        pa += elu1(acc[nt][0] + b2s[nc]) * w0 + elu1(acc[nt][1] + b2s[nc + 1]) * w1;
        pb += elu1(acc[nt][2] + b2s[nc]) * w0 + elu1(acc[nt][3] + b2s[nc + 1]) * w1;
    }
    pa += __shfl_xor_sync(0xffffffff, pa, 1);
    pa += __shfl_xor_sync(0xffffffff, pa, 2);
    pb += __shfl_xor_sync(0xffffffff, pb, 1);
    pb += __shfl_xor_sync(0xffffffff, pb, 2);
    float* red = (float*)(smem + (nw ? SM_R1 : SM_R0));
    if (tig == 0) {
        red[e0 + gid] = pa;
        red[e0 + gid + 8] = pb;
    }
    __syncthreads();
    if (tid < 64 && tid < nv) {
        float* r0 = (float*)(smem + SM_R0);
        float* r1 = (float*)(smem + SM_R1);
        out[tile + tid] = r0[tid] + r1[tid] + __ldg(b3);
    }
}

extern "C" void kernel_launch(void* const* d_in, const int* in_sizes, int n_in,
                              void* d_out, int out_size) {
    const float* x  = (const float*)d_in[0];
    const void*  ei = d_in[1];
    const float* W1 = (const float*)d_in[2];
    const float* b1 = (const float*)d_in[3];
    const float* W2 = (const float*)d_in[4];
    const float* b2 = (const float*)d_in[5];
    const float* W3 = (const float*)d_in[6];
    const float* b3 = (const float*)d_in[7];
    float* out = (float*)d_out;

    const int n_edges = out_size;
    const int n_nodes = in_sizes[0] / 128;

    cudaFuncSetAttribute(edge_mlp_hmma_kernel,
                         cudaFuncAttributeMaxDynamicSharedMemorySize, SMEM_BYTES);

    wconv_kernel<<<192, 256>>>(W1, W2);
    const int grid = (n_edges + EPT - 1) / EPT;
    edge_mlp_hmma_kernel<<<grid, THREADS, SMEM_BYTES>>>(x, ei, b1, b2, W3, b3,
                                                        out, n_edges, n_nodes);
}